// round 3
// baseline (speedup 1.0000x reference)
#include <cuda_runtime.h>
#include <cstdint>

#define kB   4
#define kDEC 256
#define kENC 1024
#define kHID 512
#define kU   128

// 512(qs) + 128(scl) + 4096(sc) + 128*132(ks) + 16(red) floats
#define SCORE_SMEM_FLOATS (512 + 128 + 4096 + 128*132 + 16)
#define SCORE_SMEM_BYTES  (SCORE_SMEM_FLOATS * 4)

__device__ float g_q[kB * kDEC * kU];
__device__ float g_k[kB * kENC * kU];

__device__ __forceinline__ float tanh_approx(float x) {
    float y;
    asm("tanh.approx.f32 %0, %1;" : "=f"(y) : "f"(x));
    return y;
}

// ---------------------------------------------------------------------------
// Generic row-major tiled GEMM: C[M,N] = A[M,K] * B[K,N], 64x64 tile, K-chunk 16
// Batched via blockIdx.z with element strides sA/sB/sC.
// ---------------------------------------------------------------------------
__global__ __launch_bounds__(256) void gemm64_kernel(
    const float* __restrict__ A, const float* __restrict__ Bm, float* __restrict__ C,
    int M, int N, int K, long sA, long sB, long sC)
{
    const float* Ab = A + (long)blockIdx.z * sA;
    const float* Bb = Bm + (long)blockIdx.z * sB;
    float*       Cb = C + (long)blockIdx.z * sC;
    const int m0 = blockIdx.y * 64;
    const int n0 = blockIdx.x * 64;

    __shared__ float As[16][68];   // [kk][m], padded
    __shared__ float Bs[16][64];   // [kk][n]

    const int tid = threadIdx.x;
    const int tx = tid & 15, ty = tid >> 4;

    float acc[4][4];
#pragma unroll
    for (int i = 0; i < 4; i++)
#pragma unroll
        for (int j = 0; j < 4; j++) acc[i][j] = 0.f;

    for (int kt = 0; kt < K; kt += 16) {
#pragma unroll
        for (int i = 0; i < 4; i++) {
            int idx = tid * 4 + i;            // 0..1023
            int m = idx >> 4, kk = idx & 15;
            As[kk][m] = Ab[(long)(m0 + m) * K + kt + kk];
        }
#pragma unroll
        for (int i = 0; i < 4; i++) {
            int idx = tid + 256 * i;          // 0..1023
            int kk = idx >> 6, n = idx & 63;
            Bs[kk][n] = Bb[(long)(kt + kk) * N + n0 + n];
        }
        __syncthreads();
#pragma unroll
        for (int kk = 0; kk < 16; kk++) {
            float a[4], b[4];
#pragma unroll
            for (int i = 0; i < 4; i++) a[i] = As[kk][ty * 4 + i];
#pragma unroll
            for (int j = 0; j < 4; j++) b[j] = Bs[kk][tx * 4 + j];
#pragma unroll
            for (int i = 0; i < 4; i++)
#pragma unroll
                for (int j = 0; j < 4; j++)
                    acc[i][j] = fmaf(a[i], b[j], acc[i][j]);
        }
        __syncthreads();
    }
#pragma unroll
    for (int i = 0; i < 4; i++)
#pragma unroll
        for (int j = 0; j < 4; j++)
            Cb[(long)(m0 + ty * 4 + i) * N + n0 + tx * 4 + j] = acc[i][j];
}

// ---------------------------------------------------------------------------
// Fused additive scores + masked softmax.
// One block = (batch b, 4 decoder queries). 256 threads.
// Thread layout: q = tid>>6 (0..3), eidx = tid&63; each thread handles
// e-rows {eidx, eidx+64} of the current 128-row k tile.
// ks padded to stride 132 floats -> float4 LDS is bank-conflict-free
// (lane-to-lane byte delta 528 == 16 mod 128).
// ---------------------------------------------------------------------------
__global__ __launch_bounds__(256) void score_softmax_kernel(
    const float* __restrict__ scale, const int* __restrict__ mask,
    float* __restrict__ wts)
{
    extern __shared__ float sm[];
    float* qs  = sm;                  // 4 * 128
    float* scl = qs + 4 * kU;         // 128
    float* sc  = scl + kU;            // 4 * kENC
    float* ks  = sc + 4 * kENC;       // 128 * 132
    float* red = ks + 128 * 132;      // 16

    const int bq = blockIdx.x;
    const int b  = bq >> 6;           // DEC/4 = 64 q-tiles per batch
    const int q0 = (bq & 63) * 4;
    const int tid = threadIdx.x;

    // load 4 query rows (512 floats) with 256 threads: 2 each
#pragma unroll
    for (int i = 0; i < 2; i++)
        qs[tid + i * 256] = g_q[(b * kDEC + q0) * kU + tid + i * 256];
    if (tid < kU) scl[tid] = scale[tid];

    const int q    = tid >> 6;
    const int eidx = tid & 63;
    const float* kbase = g_k + (long)b * kENC * kU;
    const int*   mrow  = mask + b * kENC;

    for (int et = 0; et < kENC; et += 128) {
        __syncthreads();              // protect ks reuse (also orders qs/scl fill)
        // stage k tile [128 x 128] -> ks (stride 132), coalesced float4 loads
#pragma unroll
        for (int i = 0; i < 16; i++) {
            int f4  = tid + i * 256;          // 0..4095 float4s
            int row = f4 >> 5;
            int col = (f4 & 31) * 4;
            float4 v = *(const float4*)(kbase + (long)(et + row) * kU + col);
            *(float4*)(ks + row * 132 + col) = v;
        }
        __syncthreads();

        const float* ka = ks + eidx * 132;
        const float* kb = ks + (eidx + 64) * 132;
        const float* qr = qs + q * kU;
        float s0 = 0.f, s1 = 0.f;
#pragma unroll
        for (int u = 0; u < kU; u += 4) {
            float4 kva = *(const float4*)(ka + u);
            float4 kvb = *(const float4*)(kb + u);
            float4 qv  = *(const float4*)(qr + u);
            float4 sv  = *(const float4*)(scl + u);
            s0 = fmaf(sv.x, tanh_approx(qv.x + kva.x), s0);
            s0 = fmaf(sv.y, tanh_approx(qv.y + kva.y), s0);
            s0 = fmaf(sv.z, tanh_approx(qv.z + kva.z), s0);
            s0 = fmaf(sv.w, tanh_approx(qv.w + kva.w), s0);
            s1 = fmaf(sv.x, tanh_approx(qv.x + kvb.x), s1);
            s1 = fmaf(sv.y, tanh_approx(qv.y + kvb.y), s1);
            s1 = fmaf(sv.z, tanh_approx(qv.z + kvb.z), s1);
            s1 = fmaf(sv.w, tanh_approx(qv.w + kvb.w), s1);
        }
        const int ea = et + eidx, eb = ea + 64;
        if (mrow[ea] == 0) s0 = -1e9f;
        if (mrow[eb] == 0) s1 = -1e9f;
        sc[q * kENC + ea] = s0;
        sc[q * kENC + eb] = s1;
    }
    __syncthreads();

    // masked softmax: row r handled by 64 threads (2 aligned warps)
    const int r  = tid >> 6;
    const int lg = tid & 63;
    float* row = sc + r * kENC;

    float mx = -3.4e38f;
#pragma unroll
    for (int j = 0; j < 16; j++) mx = fmaxf(mx, row[lg + j * 64]);
#pragma unroll
    for (int off = 16; off > 0; off >>= 1)
        mx = fmaxf(mx, __shfl_xor_sync(0xffffffffu, mx, off));
    const int warp = tid >> 5;
    if ((tid & 31) == 0) red[warp] = mx;
    __syncthreads();
    mx = fmaxf(red[r * 2], red[r * 2 + 1]);

    float ssum = 0.f;
#pragma unroll
    for (int j = 0; j < 16; j++) {
        float p = __expf(row[lg + j * 64] - mx);
        row[lg + j * 64] = p;
        ssum += p;
    }
#pragma unroll
    for (int off = 16; off > 0; off >>= 1)
        ssum += __shfl_xor_sync(0xffffffffu, ssum, off);
    if ((tid & 31) == 0) red[8 + warp] = ssum;
    __syncthreads();
    ssum = red[8 + r * 2] + red[8 + r * 2 + 1];
    const float inv = 1.0f / ssum;

    float* wrow = wts + (long)(b * kDEC + q0 + r) * kENC;
#pragma unroll
    for (int j = 0; j < 16; j++)
        wrow[lg + j * 64] = row[lg + j * 64] * inv;
}

// ---------------------------------------------------------------------------
extern "C" void kernel_launch(void* const* d_in, const int* in_sizes, int n_in,
                              void* d_out, int out_size)
{
    const float* query = (const float*)d_in[0];
    const float* value = (const float*)d_in[1];
    const int*   mask  = (const int*)d_in[2];     // jax bool -> int32 on upload
    const float* W1    = (const float*)d_in[3];
    const float* W2    = (const float*)d_in[4];
    const float* scale = (const float*)d_in[5];

    float* ctx = (float*)d_out;                          // (B, DEC, HID)
    float* wts = ctx + (size_t)kB * kDEC * kHID;         // (B, DEC, ENC)

    float *qptr, *kptr;
    cudaGetSymbolAddress((void**)&qptr, g_q);
    cudaGetSymbolAddress((void**)&kptr, g_k);

    cudaFuncSetAttribute(score_softmax_kernel,
        cudaFuncAttributeMaxDynamicSharedMemorySize, SCORE_SMEM_BYTES);

    // q projection: (B*DEC, HID) @ (HID, U)
    gemm64_kernel<<<dim3(kU / 64, (kB * kDEC) / 64, 1), 256>>>(
        query, W1, qptr, kB * kDEC, kU, kHID, 0, 0, 0);

    // k projection: (B*ENC, HID) @ (HID, U)
    gemm64_kernel<<<dim3(kU / 64, (kB * kENC) / 64, 1), 256>>>(
        value, W2, kptr, kB * kENC, kU, kHID, 0, 0, 0);

    // fused scores + masked softmax -> weights
    score_softmax_kernel<<<kB * 64, 256, SCORE_SMEM_BYTES>>>(scale, mask, wts);

    // context: per-batch (DEC, ENC) @ (ENC, HID)
    gemm64_kernel<<<dim3(kHID / 64, kDEC / 64, kB), 256>>>(
        wts, value, ctx, kDEC, kHID, kENC,
        (long)kDEC * kENC, (long)kENC * kHID, (long)kDEC * kHID);
}

// round 4
// speedup vs baseline: 1.3361x; 1.3361x over previous
#include <cuda_runtime.h>
#include <cstdint>

#define kB   4
#define kDEC 256
#define kENC 1024
#define kHID 512
#define kU   128

#define QP_STRIDE (1024 * 128)   // one qproj part (M=1024, N=128)
#define KP_STRIDE (4096 * 128)   // one kproj part (M=4096, N=128)
#define CP_STRIDE (256 * 512)    // one ctx part   (M=256,  N=512)

// 512(qs) + 128(scl) + 4096(sc) + 128*132(ks) + 16(red) floats
#define SCORE_SMEM_FLOATS (512 + 128 + 4096 + 128*132 + 16)
#define SCORE_SMEM_BYTES  (SCORE_SMEM_FLOATS * 4)

__device__ float g_qp[4 * QP_STRIDE];   // 4 K-split parts of q projection
__device__ float g_kp[2 * KP_STRIDE];   // 2 K-split parts of k projection
__device__ float g_cp[16 * CP_STRIDE];  // (batch,split) parts of context

__device__ __forceinline__ float tanh_approx(float x) {
    float y;
    asm("tanh.approx.f32 %0, %1;" : "=f"(y) : "f"(x));
    return y;
}

__device__ __forceinline__ unsigned long long pack2(float x, float y) {
    unsigned long long r;
    asm("mov.b64 %0, {%1, %2};" : "=l"(r) : "f"(x), "f"(y));
    return r;
}
__device__ __forceinline__ float2 unpack2(unsigned long long v) {
    float2 f;
    asm("mov.b64 {%0, %1}, %2;" : "=f"(f.x), "=f"(f.y) : "l"(v));
    return f;
}
__device__ __forceinline__ void fma2(unsigned long long& d,
                                     unsigned long long a, unsigned long long b) {
    asm("fma.rn.f32x2 %0, %1, %2, %0;" : "+l"(d) : "l"(a), "l"(b));
}

// ---------------------------------------------------------------------------
// f32x2 tiled GEMM with deterministic K-split.
// C_part[z][M,N] = A_b[M, Ks] * B_b[Ks, N] over K-slice s, z = b*nsplit + s.
// Tile 64x64, 256 threads, micro 4x4 (4 m-rows x 2 f32x2 n-pairs).
// ---------------------------------------------------------------------------
__global__ __launch_bounds__(256) void gemm_f32x2(
    const float* __restrict__ A, const float* __restrict__ Bm, float* __restrict__ C,
    int M, int N, int K, int nsplit, long sA, long sB)
{
    const int z = blockIdx.z;
    const int b = z / nsplit;
    const int s = z - b * nsplit;
    const int Klocal = K / nsplit;
    const int kbeg = s * Klocal;

    const float* Ab = A + (long)b * sA;
    const float* Bb = Bm + (long)b * sB;
    float*       Cb = C + (long)z * M * N;

    const int m0 = blockIdx.y * 64;
    const int n0 = blockIdx.x * 64;

    __shared__ float As[16][72];   // [kk][m], 288B rows -> 16B-aligned float4 reads
    __shared__ float Bs[16][64];   // [kk][n]

    const int tid = threadIdx.x;
    const int tx = tid & 15, ty = tid >> 4;

    // A fill indices: each thread loads one float4 along K
    const int am = tid >> 2;          // 0..63
    const int ak = (tid & 3) * 4;     // 0,4,8,12
    // B fill indices: one float4 along N
    const int bk = tid >> 4;          // 0..15
    const int bn = (tid & 15) * 4;    // 0..60

    unsigned long long acc[4][2];
#pragma unroll
    for (int i = 0; i < 4; i++) { acc[i][0] = 0ull; acc[i][1] = 0ull; }

    for (int kt = kbeg; kt < kbeg + Klocal; kt += 16) {
        float4 av = *(const float4*)&Ab[(long)(m0 + am) * K + kt + ak];
        float4 bv = *(const float4*)&Bb[(long)(kt + bk) * N + n0 + bn];
        As[ak + 0][am] = av.x;
        As[ak + 1][am] = av.y;
        As[ak + 2][am] = av.z;
        As[ak + 3][am] = av.w;
        *(float4*)&Bs[bk][bn] = bv;
        __syncthreads();
#pragma unroll
        for (int kk = 0; kk < 16; kk++) {
            float4 a = *(const float4*)&As[kk][ty * 4];
            float4 bvv = *(const float4*)&Bs[kk][tx * 4];
            unsigned long long b01 = pack2(bvv.x, bvv.y);
            unsigned long long b23 = pack2(bvv.z, bvv.w);
            unsigned long long a0 = pack2(a.x, a.x);
            unsigned long long a1 = pack2(a.y, a.y);
            unsigned long long a2 = pack2(a.z, a.z);
            unsigned long long a3 = pack2(a.w, a.w);
            fma2(acc[0][0], a0, b01); fma2(acc[0][1], a0, b23);
            fma2(acc[1][0], a1, b01); fma2(acc[1][1], a1, b23);
            fma2(acc[2][0], a2, b01); fma2(acc[2][1], a2, b23);
            fma2(acc[3][0], a3, b01); fma2(acc[3][1], a3, b23);
        }
        __syncthreads();
    }
#pragma unroll
    for (int i = 0; i < 4; i++) {
        float2 c0 = unpack2(acc[i][0]);
        float2 c1 = unpack2(acc[i][1]);
        float4 o = make_float4(c0.x, c0.y, c1.x, c1.y);
        *(float4*)&Cb[(long)(m0 + ty * 4 + i) * N + n0 + tx * 4] = o;
    }
}

// ---------------------------------------------------------------------------
// ctx[b][i] = sum over 4 K-split parts. float4-vectorized.
// ---------------------------------------------------------------------------
__global__ __launch_bounds__(256) void reduce_ctx_kernel(float4* __restrict__ out)
{
    const float4* p = (const float4*)g_cp;
    const int idx = blockIdx.x * 256 + threadIdx.x;     // 0 .. B*CP/4-1
    const int slice = CP_STRIDE / 4;                    // 32768
    const int b = idx / slice;
    const int i = idx - b * slice;
    const float4* base = p + (long)(b * 4) * slice + i;
    float4 r0 = base[0], r1 = base[slice], r2 = base[2 * slice], r3 = base[3 * slice];
    out[idx] = make_float4(r0.x + r1.x + r2.x + r3.x,
                           r0.y + r1.y + r2.y + r3.y,
                           r0.z + r1.z + r2.z + r3.z,
                           r0.w + r1.w + r2.w + r3.w);
}

// ---------------------------------------------------------------------------
// Fused additive scores + masked softmax. One block = (batch b, 4 queries).
// q/k are read as sums of the projection K-split parts (deterministic).
// ---------------------------------------------------------------------------
__global__ __launch_bounds__(256) void score_softmax_kernel(
    const float* __restrict__ scale, const int* __restrict__ mask,
    float* __restrict__ wts)
{
    extern __shared__ float sm[];
    float* qs  = sm;                  // 4 * 128
    float* scl = qs + 4 * kU;         // 128
    float* sc  = scl + kU;            // 4 * kENC
    float* ks  = sc + 4 * kENC;       // 128 * 132
    float* red = ks + 128 * 132;      // 16

    const int bq = blockIdx.x;
    const int b  = bq >> 6;           // DEC/4 = 64 q-tiles per batch
    const int q0 = (bq & 63) * 4;
    const int tid = threadIdx.x;

    // stage 4 query rows: sum the 4 qproj K-split parts
#pragma unroll
    for (int i = 0; i < 2; i++) {
        int idx = (b * kDEC + q0) * kU + tid + i * 256;
        qs[tid + i * 256] = g_qp[idx] + g_qp[idx + QP_STRIDE]
                          + g_qp[idx + 2 * QP_STRIDE] + g_qp[idx + 3 * QP_STRIDE];
    }
    if (tid < kU) scl[tid] = scale[tid];

    const int q    = tid >> 6;
    const int eidx = tid & 63;
    const float* kbase = g_kp + (long)b * kENC * kU;
    const int*   mrow  = mask + b * kENC;

    for (int et = 0; et < kENC; et += 128) {
        __syncthreads();              // protect ks reuse (also orders qs/scl fill)
        // stage k tile [128 x 128] -> ks (stride 132), summing 2 kproj parts
#pragma unroll
        for (int i = 0; i < 16; i++) {
            int f4  = tid + i * 256;          // 0..4095 float4s
            int row = f4 >> 5;
            int col = (f4 & 31) * 4;
            const float* src = kbase + (long)(et + row) * kU + col;
            float4 v0 = *(const float4*)src;
            float4 v1 = *(const float4*)(src + KP_STRIDE);
            *(float4*)(ks + row * 132 + col) =
                make_float4(v0.x + v1.x, v0.y + v1.y, v0.z + v1.z, v0.w + v1.w);
        }
        __syncthreads();

        const float* ka = ks + eidx * 132;
        const float* kb = ks + (eidx + 64) * 132;
        const float* qr = qs + q * kU;
        float s0 = 0.f, s1 = 0.f;
#pragma unroll
        for (int u = 0; u < kU; u += 4) {
            float4 kva = *(const float4*)(ka + u);
            float4 kvb = *(const float4*)(kb + u);
            float4 qv  = *(const float4*)(qr + u);
            float4 sv  = *(const float4*)(scl + u);
            s0 = fmaf(sv.x, tanh_approx(qv.x + kva.x), s0);
            s0 = fmaf(sv.y, tanh_approx(qv.y + kva.y), s0);
            s0 = fmaf(sv.z, tanh_approx(qv.z + kva.z), s0);
            s0 = fmaf(sv.w, tanh_approx(qv.w + kva.w), s0);
            s1 = fmaf(sv.x, tanh_approx(qv.x + kvb.x), s1);
            s1 = fmaf(sv.y, tanh_approx(qv.y + kvb.y), s1);
            s1 = fmaf(sv.z, tanh_approx(qv.z + kvb.z), s1);
            s1 = fmaf(sv.w, tanh_approx(qv.w + kvb.w), s1);
        }
        const int ea = et + eidx, eb = ea + 64;
        if (mrow[ea] == 0) s0 = -1e9f;
        if (mrow[eb] == 0) s1 = -1e9f;
        sc[q * kENC + ea] = s0;
        sc[q * kENC + eb] = s1;
    }
    __syncthreads();

    // masked softmax: row r handled by 64 threads (2 aligned warps)
    const int r  = tid >> 6;
    const int lg = tid & 63;
    float* row = sc + r * kENC;

    float mx = -3.4e38f;
#pragma unroll
    for (int j = 0; j < 16; j++) mx = fmaxf(mx, row[lg + j * 64]);
#pragma unroll
    for (int off = 16; off > 0; off >>= 1)
        mx = fmaxf(mx, __shfl_xor_sync(0xffffffffu, mx, off));
    const int warp = tid >> 5;
    if ((tid & 31) == 0) red[warp] = mx;
    __syncthreads();
    mx = fmaxf(red[r * 2], red[r * 2 + 1]);

    float ssum = 0.f;
#pragma unroll
    for (int j = 0; j < 16; j++) {
        float p = __expf(row[lg + j * 64] - mx);
        row[lg + j * 64] = p;
        ssum += p;
    }
#pragma unroll
    for (int off = 16; off > 0; off >>= 1)
        ssum += __shfl_xor_sync(0xffffffffu, ssum, off);
    if ((tid & 31) == 0) red[8 + warp] = ssum;
    __syncthreads();
    ssum = red[8 + r * 2] + red[8 + r * 2 + 1];
    const float inv = 1.0f / ssum;

    float* wrow = wts + (long)(b * kDEC + q0 + r) * kENC;
#pragma unroll
    for (int j = 0; j < 16; j++)
        wrow[lg + j * 64] = row[lg + j * 64] * inv;
}

// ---------------------------------------------------------------------------
extern "C" void kernel_launch(void* const* d_in, const int* in_sizes, int n_in,
                              void* d_out, int out_size)
{
    const float* query = (const float*)d_in[0];
    const float* value = (const float*)d_in[1];
    const int*   mask  = (const int*)d_in[2];     // jax bool -> int32 on upload
    const float* W1    = (const float*)d_in[3];
    const float* W2    = (const float*)d_in[4];
    const float* scale = (const float*)d_in[5];

    float* ctx = (float*)d_out;                          // (B, DEC, HID)
    float* wts = ctx + (size_t)kB * kDEC * kHID;         // (B, DEC, ENC)

    float *qp, *kp, *cp;
    cudaGetSymbolAddress((void**)&qp, g_qp);
    cudaGetSymbolAddress((void**)&kp, g_kp);
    cudaGetSymbolAddress((void**)&cp, g_cp);

    cudaFuncSetAttribute(score_softmax_kernel,
        cudaFuncAttributeMaxDynamicSharedMemorySize, SCORE_SMEM_BYTES);

    // q projection: (1024, 512) @ (512, 128), K-split 4 -> 128 blocks
    gemm_f32x2<<<dim3(2, 16, 4), 256>>>(query, W1, qp, 1024, 128, 512, 4, 0, 0);

    // k projection: (4096, 512) @ (512, 128), K-split 2 -> 256 blocks
    gemm_f32x2<<<dim3(2, 64, 2), 256>>>(value, W2, kp, 4096, 128, 512, 2, 0, 0);

    // fused scores + masked softmax -> weights
    score_softmax_kernel<<<kB * 64, 256, SCORE_SMEM_BYTES>>>(scale, mask, wts);

    // context: per-batch (256, 1024) @ (1024, 512), K-split 4 -> 512 blocks
    gemm_f32x2<<<dim3(8, 4, 16), 256>>>(wts, value, cp, 256, 512, 1024, 4,
                                        (long)kDEC * kENC, (long)kENC * kHID);

    // sum the 4 ctx parts -> d_out
    reduce_ctx_kernel<<<(kB * CP_STRIDE / 4) / 256, 256>>>((float4*)ctx);
}

// round 5
// speedup vs baseline: 1.4315x; 1.0714x over previous
#include <cuda_runtime.h>
#include <cstdint>

#define kB   4
#define kDEC 256
#define kENC 1024
#define kHID 512
#define kU   128

#define QSPLIT 16
#define KSPLIT 4
#define CSPLIT 4

#define QP_STRIDE (1024 * 128)   // one qproj part
#define KP_STRIDE (4096 * 128)   // one kproj part
#define CP_STRIDE (256 * 512)    // one ctx part

// score smem: 1024(qs)+128(scl)+8192(sc)+128*132(ks) floats
#define SCORE_SMEM_FLOATS (1024 + 128 + 8192 + 128*132)
#define SCORE_SMEM_BYTES  (SCORE_SMEM_FLOATS * 4)

__device__ float g_qp[QSPLIT * QP_STRIDE];
__device__ float g_kp[KSPLIT * KP_STRIDE];
__device__ float g_q[kB * kDEC * kU];
__device__ float g_k[kB * kENC * kU];
__device__ float g_cp[kB * CSPLIT * CP_STRIDE];

__device__ __forceinline__ float tanh_approx(float x) {
    float y;
    asm("tanh.approx.f32 %0, %1;" : "=f"(y) : "f"(x));
    return y;
}
__device__ __forceinline__ unsigned long long pack2(float x, float y) {
    unsigned long long r;
    asm("mov.b64 %0, {%1, %2};" : "=l"(r) : "f"(x), "f"(y));
    return r;
}
__device__ __forceinline__ float2 unpack2(unsigned long long v) {
    float2 f;
    asm("mov.b64 {%0, %1}, %2;" : "=f"(f.x), "=f"(f.y) : "l"(v));
    return f;
}
__device__ __forceinline__ void fma2(unsigned long long& d,
                                     unsigned long long a, unsigned long long b) {
    asm("fma.rn.f32x2 %0, %1, %2, %0;" : "+l"(d) : "l"(a), "l"(b));
}

// ---------------------------------------------------------------------------
// f32x2 GEMM, 128x128 tile, 8x8 micro, deterministic K-split.
// C_part[z][M,N] = A_b[M,Ks] * B_b[Ks,N], z = b*nsplit + s.
// ---------------------------------------------------------------------------
__global__ __launch_bounds__(256) void gemm128(
    const float* __restrict__ A, const float* __restrict__ Bm, float* __restrict__ C,
    int M, int N, int K, int nsplit, long sA, long sB)
{
    __shared__ float As[16][132];   // [kk][m]
    __shared__ float Bs[16][128];   // [kk][n]

    const int z = blockIdx.z;
    const int b = z / nsplit;
    const int s = z - b * nsplit;
    const int Klocal = K / nsplit;
    const int kbeg = s * Klocal;

    const float* Ab = A + (long)b * sA;
    const float* Bb = Bm + (long)b * sB;
    float*       Cb = C + (long)z * M * N;

    const int m0 = blockIdx.y * 128;
    const int n0 = blockIdx.x * 128;

    const int tid = threadIdx.x;
    const int tx = tid & 15, ty = tid >> 4;

    const int am = tid >> 1,  ak = (tid & 1) * 8;   // A: 8 k-floats of row am
    const int bk = tid >> 4,  bn = (tid & 15) * 8;  // B: 8 n-floats of row bk

    const float* Aptr = Ab + (long)(m0 + am) * K + kbeg + ak;
    const float* Bptr = Bb + (long)(kbeg + bk) * N + n0 + bn;

    unsigned long long acc[8][4];
#pragma unroll
    for (int i = 0; i < 8; i++)
#pragma unroll
        for (int j = 0; j < 4; j++) acc[i][j] = 0ull;

    float4 a0 = *(const float4*)(Aptr);
    float4 a1 = *(const float4*)(Aptr + 4);
    float4 b0 = *(const float4*)(Bptr);
    float4 b1 = *(const float4*)(Bptr + 4);

    for (int kt = 0; kt < Klocal; kt += 16) {
        As[ak + 0][am] = a0.x; As[ak + 1][am] = a0.y;
        As[ak + 2][am] = a0.z; As[ak + 3][am] = a0.w;
        As[ak + 4][am] = a1.x; As[ak + 5][am] = a1.y;
        As[ak + 6][am] = a1.z; As[ak + 7][am] = a1.w;
        *(float4*)&Bs[bk][bn]     = b0;
        *(float4*)&Bs[bk][bn + 4] = b1;
        __syncthreads();

        // prefetch next tile (clamped to valid address on last iter)
        int kn = (kt + 16 < Klocal) ? kt + 16 : 0;
        a0 = *(const float4*)(Aptr + kn);
        a1 = *(const float4*)(Aptr + kn + 4);
        b0 = *(const float4*)(Bptr + (long)kn * N);
        b1 = *(const float4*)(Bptr + (long)kn * N + 4);

#pragma unroll
        for (int kk = 0; kk < 16; kk++) {
            float4 av0 = *(const float4*)&As[kk][ty * 8];
            float4 av1 = *(const float4*)&As[kk][ty * 8 + 4];
            float4 bv0 = *(const float4*)&Bs[kk][tx * 8];
            float4 bv1 = *(const float4*)&Bs[kk][tx * 8 + 4];
            unsigned long long bp0 = pack2(bv0.x, bv0.y);
            unsigned long long bp1 = pack2(bv0.z, bv0.w);
            unsigned long long bp2 = pack2(bv1.x, bv1.y);
            unsigned long long bp3 = pack2(bv1.z, bv1.w);
            float av[8] = {av0.x, av0.y, av0.z, av0.w, av1.x, av1.y, av1.z, av1.w};
#pragma unroll
            for (int i = 0; i < 8; i++) {
                unsigned long long ap = pack2(av[i], av[i]);
                fma2(acc[i][0], ap, bp0);
                fma2(acc[i][1], ap, bp1);
                fma2(acc[i][2], ap, bp2);
                fma2(acc[i][3], ap, bp3);
            }
        }
        __syncthreads();
    }

#pragma unroll
    for (int i = 0; i < 8; i++) {
        float2 c0 = unpack2(acc[i][0]), c1 = unpack2(acc[i][1]);
        float2 c2 = unpack2(acc[i][2]), c3 = unpack2(acc[i][3]);
        float* crow = Cb + (long)(m0 + ty * 8 + i) * N + n0 + tx * 8;
        *(float4*)crow       = make_float4(c0.x, c0.y, c1.x, c1.y);
        *(float4*)(crow + 4) = make_float4(c2.x, c2.y, c3.x, c3.y);
    }
}

// ---------------------------------------------------------------------------
// Sum projection K-split parts: g_qp(16) -> g_q, g_kp(4) -> g_k.
// ---------------------------------------------------------------------------
#define QN (kB * kDEC * kU / 4)    // 32768 float4
#define KN (kB * kENC * kU / 4)    // 131072 float4
__global__ __launch_bounds__(256) void reduce_qk_kernel()
{
    int idx = blockIdx.x * 256 + threadIdx.x;
    if (idx < QN) {
        const float4* p = (const float4*)g_qp;
        float4 s = make_float4(0.f, 0.f, 0.f, 0.f);
#pragma unroll
        for (int j = 0; j < QSPLIT; j++) {
            float4 v = p[idx + j * (QP_STRIDE / 4)];
            s.x += v.x; s.y += v.y; s.z += v.z; s.w += v.w;
        }
        ((float4*)g_q)[idx] = s;
    } else {
        int i = idx - QN;
        const float4* p = (const float4*)g_kp;
        float4 s = make_float4(0.f, 0.f, 0.f, 0.f);
#pragma unroll
        for (int j = 0; j < KSPLIT; j++) {
            float4 v = p[i + j * (KP_STRIDE / 4)];
            s.x += v.x; s.y += v.y; s.z += v.z; s.w += v.w;
        }
        ((float4*)g_k)[i] = s;
    }
}

// ---------------------------------------------------------------------------
// ctx = sum of 4 K-split parts per batch.
// ---------------------------------------------------------------------------
__global__ __launch_bounds__(256) void reduce_ctx_kernel(float4* __restrict__ out)
{
    const float4* p = (const float4*)g_cp;
    const int idx = blockIdx.x * 256 + threadIdx.x;
    const int slice = CP_STRIDE / 4;
    const int b = idx / slice;
    const int i = idx - b * slice;
    const float4* base = p + (long)(b * CSPLIT) * slice + i;
    float4 r0 = base[0], r1 = base[slice], r2 = base[2 * slice], r3 = base[3 * slice];
    out[idx] = make_float4(r0.x + r1.x + r2.x + r3.x,
                           r0.y + r1.y + r2.y + r3.y,
                           r0.z + r1.z + r2.z + r3.z,
                           r0.w + r1.w + r2.w + r3.w);
}

// ---------------------------------------------------------------------------
// Fused additive scores + masked softmax. One block = (batch b, 8 queries).
// 256 threads: warp w owns query q0+w; lane handles 4 e-rows per 128-tile.
// ---------------------------------------------------------------------------
__global__ __launch_bounds__(256) void score_softmax_kernel(
    const float* __restrict__ scale, const int* __restrict__ mask,
    float* __restrict__ wts)
{
    extern __shared__ float sm[];
    float* qs  = sm;                  // 8 * 128
    float* scl = qs + 8 * kU;         // 128
    float* sc  = scl + kU;            // 8 * kENC
    float* ks  = sc + 8 * kENC;       // 128 * 132

    const int bq = blockIdx.x;
    const int b  = bq >> 5;           // 32 q-tiles of 8 per batch
    const int q0 = (bq & 31) * 8;
    const int tid = threadIdx.x;

#pragma unroll
    for (int i = 0; i < 4; i++)
        qs[tid + i * 256] = g_q[(b * kDEC + q0) * kU + tid + i * 256];
    if (tid < kU) scl[tid] = scale[tid];

    const int q    = tid >> 5;        // warp id = query row
    const int lane = tid & 31;
    const float* kbase = g_k + (long)b * kENC * kU;
    const int*   mrow  = mask + b * kENC;
    const float* qr = qs + q * kU;

    for (int et = 0; et < kENC; et += 128) {
        __syncthreads();
#pragma unroll
        for (int i = 0; i < 16; i++) {
            int f4  = tid + i * 256;           // 0..4095
            int row = f4 >> 5;
            int col = (f4 & 31) * 4;
            *(float4*)(ks + row * 132 + col) =
                *(const float4*)(kbase + (long)(et + row) * kU + col);
        }
        __syncthreads();

        const float* k0 = ks + (lane +  0) * 132;
        const float* k1 = ks + (lane + 32) * 132;
        const float* k2 = ks + (lane + 64) * 132;
        const float* k3 = ks + (lane + 96) * 132;
        float s0 = 0.f, s1 = 0.f, s2 = 0.f, s3 = 0.f;
#pragma unroll
        for (int u = 0; u < kU; u += 4) {
            float4 qv = *(const float4*)(qr + u);
            float4 sv = *(const float4*)(scl + u);
            float4 a = *(const float4*)(k0 + u);
            float4 c = *(const float4*)(k1 + u);
            float4 d = *(const float4*)(k2 + u);
            float4 e = *(const float4*)(k3 + u);
            s0 = fmaf(sv.x, tanh_approx(qv.x + a.x), s0);
            s0 = fmaf(sv.y, tanh_approx(qv.y + a.y), s0);
            s0 = fmaf(sv.z, tanh_approx(qv.z + a.z), s0);
            s0 = fmaf(sv.w, tanh_approx(qv.w + a.w), s0);
            s1 = fmaf(sv.x, tanh_approx(qv.x + c.x), s1);
            s1 = fmaf(sv.y, tanh_approx(qv.y + c.y), s1);
            s1 = fmaf(sv.z, tanh_approx(qv.z + c.z), s1);
            s1 = fmaf(sv.w, tanh_approx(qv.w + c.w), s1);
            s2 = fmaf(sv.x, tanh_approx(qv.x + d.x), s2);
            s2 = fmaf(sv.y, tanh_approx(qv.y + d.y), s2);
            s2 = fmaf(sv.z, tanh_approx(qv.z + d.z), s2);
            s2 = fmaf(sv.w, tanh_approx(qv.w + d.w), s2);
            s3 = fmaf(sv.x, tanh_approx(qv.x + e.x), s3);
            s3 = fmaf(sv.y, tanh_approx(qv.y + e.y), s3);
            s3 = fmaf(sv.z, tanh_approx(qv.z + e.z), s3);
            s3 = fmaf(sv.w, tanh_approx(qv.w + e.w), s3);
        }
        int e0 = et + lane, e1 = e0 + 32, e2 = e0 + 64, e3 = e0 + 96;
        if (mrow[e0] == 0) s0 = -1e9f;
        if (mrow[e1] == 0) s1 = -1e9f;
        if (mrow[e2] == 0) s2 = -1e9f;
        if (mrow[e3] == 0) s3 = -1e9f;
        sc[q * kENC + e0] = s0;
        sc[q * kENC + e1] = s1;
        sc[q * kENC + e2] = s2;
        sc[q * kENC + e3] = s3;
    }
    __syncthreads();

    // softmax: warp q handles row q (256 float4s, lane-interleaved)
    float4* row4 = (float4*)(sc + q * kENC);

    float mx = -3.4e38f;
#pragma unroll
    for (int j = 0; j < 8; j++) {
        float4 v = row4[lane + j * 32];
        mx = fmaxf(mx, fmaxf(fmaxf(v.x, v.y), fmaxf(v.z, v.w)));
    }
#pragma unroll
    for (int off = 16; off > 0; off >>= 1)
        mx = fmaxf(mx, __shfl_xor_sync(0xffffffffu, mx, off));

    float ssum = 0.f;
#pragma unroll
    for (int j = 0; j < 8; j++) {
        float4 v = row4[lane + j * 32];
        v.x = __expf(v.x - mx); v.y = __expf(v.y - mx);
        v.z = __expf(v.z - mx); v.w = __expf(v.w - mx);
        row4[lane + j * 32] = v;
        ssum += v.x + v.y + v.z + v.w;
    }
#pragma unroll
    for (int off = 16; off > 0; off >>= 1)
        ssum += __shfl_xor_sync(0xffffffffu, ssum, off);
    const float inv = 1.0f / ssum;

    float4* w4 = (float4*)(wts + (long)(b * kDEC + q0 + q) * kENC);
#pragma unroll
    for (int j = 0; j < 8; j++) {
        float4 v = row4[lane + j * 32];
        w4[lane + j * 32] = make_float4(v.x * inv, v.y * inv, v.z * inv, v.w * inv);
    }
}

// ---------------------------------------------------------------------------
extern "C" void kernel_launch(void* const* d_in, const int* in_sizes, int n_in,
                              void* d_out, int out_size)
{
    const float* query = (const float*)d_in[0];
    const float* value = (const float*)d_in[1];
    const int*   mask  = (const int*)d_in[2];     // jax bool -> int32 on upload
    const float* W1    = (const float*)d_in[3];
    const float* W2    = (const float*)d_in[4];
    const float* scale = (const float*)d_in[5];

    float* ctx = (float*)d_out;                          // (B, DEC, HID)
    float* wts = ctx + (size_t)kB * kDEC * kHID;         // (B, DEC, ENC)

    float *qp, *kp, *cp;
    cudaGetSymbolAddress((void**)&qp, g_qp);
    cudaGetSymbolAddress((void**)&kp, g_kp);
    cudaGetSymbolAddress((void**)&cp, g_cp);

    cudaFuncSetAttribute(score_softmax_kernel,
        cudaFuncAttributeMaxDynamicSharedMemorySize, SCORE_SMEM_BYTES);

    // q projection: (1024,512)@(512,128), split 16 -> 128 blocks
    gemm128<<<dim3(1, 8, QSPLIT), 256>>>(query, W1, qp, 1024, 128, 512, QSPLIT, 0, 0);

    // k projection: (4096,512)@(512,128), split 4 -> 128 blocks
    gemm128<<<dim3(1, 32, KSPLIT), 256>>>(value, W2, kp, 4096, 128, 512, KSPLIT, 0, 0);

    // sum projection parts
    reduce_qk_kernel<<<(QN + KN) / 256, 256>>>();

    // fused scores + masked softmax -> weights (128 blocks, 8 queries each)
    score_softmax_kernel<<<kB * 32, 256, SCORE_SMEM_BYTES>>>(scale, mask, wts);

    // context: per-batch (256,1024)@(1024,512), split 4 -> 128 blocks
    gemm128<<<dim3(4, 2, kB * CSPLIT), 256>>>(wts, value, cp, 256, 512, 1024, CSPLIT,
                                              (long)kDEC * kENC, (long)kENC * kHID);

    // sum ctx parts -> d_out
    reduce_ctx_kernel<<<(kB * CP_STRIDE / 4) / 256, 256>>>((float4*)ctx);
}

// round 6
// speedup vs baseline: 1.5379x; 1.0743x over previous
#include <cuda_runtime.h>
#include <cstdint>

#define kB   4
#define kDEC 256
#define kENC 1024
#define kHID 512
#define kU   128

#define QSPLIT 16
#define KSPLIT 4
#define CSPLIT 4

#define QP_STRIDE (1024 * 128)   // one qproj part
#define KP_STRIDE (4096 * 128)   // one kproj part
#define CP_STRIDE (256 * 512)    // one ctx part

// score smem: 1024(qs) + 128(scl) + 128*132(ks) floats = 72,192 B -> 2 CTAs/SM
#define SCORE_SMEM_FLOATS (1024 + 128 + 128*132)
#define SCORE_SMEM_BYTES  (SCORE_SMEM_FLOATS * 4)

__device__ float g_qp[QSPLIT * QP_STRIDE];
__device__ float g_kp[KSPLIT * KP_STRIDE];
__device__ float g_q[kB * kDEC * kU];
__device__ float g_k[kB * kENC * kU];
__device__ float g_cp[kB * CSPLIT * CP_STRIDE];
__device__ float g_sc[kB * kDEC * kENC];   // raw masked scores

__device__ __forceinline__ float tanh_approx(float x) {
    float y;
    asm("tanh.approx.f32 %0, %1;" : "=f"(y) : "f"(x));
    return y;
}
__device__ __forceinline__ unsigned long long pack2(float x, float y) {
    unsigned long long r;
    asm("mov.b64 %0, {%1, %2};" : "=l"(r) : "f"(x), "f"(y));
    return r;
}
__device__ __forceinline__ float2 unpack2(unsigned long long v) {
    float2 f;
    asm("mov.b64 {%0, %1}, %2;" : "=f"(f.x), "=f"(f.y) : "l"(v));
    return f;
}
__device__ __forceinline__ void fma2(unsigned long long& d,
                                     unsigned long long a, unsigned long long b) {
    asm("fma.rn.f32x2 %0, %1, %2, %0;" : "+l"(d) : "l"(a), "l"(b));
}

// ---------------------------------------------------------------------------
// f32x2 GEMM, 128x128 tile, 8x8 micro, deterministic K-split.
// ---------------------------------------------------------------------------
__global__ __launch_bounds__(256) void gemm128(
    const float* __restrict__ A, const float* __restrict__ Bm, float* __restrict__ C,
    int M, int N, int K, int nsplit, long sA, long sB)
{
    __shared__ float As[16][132];
    __shared__ float Bs[16][128];

    const int z = blockIdx.z;
    const int b = z / nsplit;
    const int s = z - b * nsplit;
    const int Klocal = K / nsplit;
    const int kbeg = s * Klocal;

    const float* Ab = A + (long)b * sA;
    const float* Bb = Bm + (long)b * sB;
    float*       Cb = C + (long)z * M * N;

    const int m0 = blockIdx.y * 128;
    const int n0 = blockIdx.x * 128;

    const int tid = threadIdx.x;
    const int tx = tid & 15, ty = tid >> 4;

    const int am = tid >> 1,  ak = (tid & 1) * 8;
    const int bk = tid >> 4,  bn = (tid & 15) * 8;

    const float* Aptr = Ab + (long)(m0 + am) * K + kbeg + ak;
    const float* Bptr = Bb + (long)(kbeg + bk) * N + n0 + bn;

    unsigned long long acc[8][4];
#pragma unroll
    for (int i = 0; i < 8; i++)
#pragma unroll
        for (int j = 0; j < 4; j++) acc[i][j] = 0ull;

    float4 a0 = *(const float4*)(Aptr);
    float4 a1 = *(const float4*)(Aptr + 4);
    float4 b0 = *(const float4*)(Bptr);
    float4 b1 = *(const float4*)(Bptr + 4);

    for (int kt = 0; kt < Klocal; kt += 16) {
        As[ak + 0][am] = a0.x; As[ak + 1][am] = a0.y;
        As[ak + 2][am] = a0.z; As[ak + 3][am] = a0.w;
        As[ak + 4][am] = a1.x; As[ak + 5][am] = a1.y;
        As[ak + 6][am] = a1.z; As[ak + 7][am] = a1.w;
        *(float4*)&Bs[bk][bn]     = b0;
        *(float4*)&Bs[bk][bn + 4] = b1;
        __syncthreads();

        int kn = (kt + 16 < Klocal) ? kt + 16 : 0;
        a0 = *(const float4*)(Aptr + kn);
        a1 = *(const float4*)(Aptr + kn + 4);
        b0 = *(const float4*)(Bptr + (long)kn * N);
        b1 = *(const float4*)(Bptr + (long)kn * N + 4);

#pragma unroll
        for (int kk = 0; kk < 16; kk++) {
            float4 av0 = *(const float4*)&As[kk][ty * 8];
            float4 av1 = *(const float4*)&As[kk][ty * 8 + 4];
            float4 bv0 = *(const float4*)&Bs[kk][tx * 8];
            float4 bv1 = *(const float4*)&Bs[kk][tx * 8 + 4];
            unsigned long long bp0 = pack2(bv0.x, bv0.y);
            unsigned long long bp1 = pack2(bv0.z, bv0.w);
            unsigned long long bp2 = pack2(bv1.x, bv1.y);
            unsigned long long bp3 = pack2(bv1.z, bv1.w);
            float av[8] = {av0.x, av0.y, av0.z, av0.w, av1.x, av1.y, av1.z, av1.w};
#pragma unroll
            for (int i = 0; i < 8; i++) {
                unsigned long long ap = pack2(av[i], av[i]);
                fma2(acc[i][0], ap, bp0);
                fma2(acc[i][1], ap, bp1);
                fma2(acc[i][2], ap, bp2);
                fma2(acc[i][3], ap, bp3);
            }
        }
        __syncthreads();
    }

#pragma unroll
    for (int i = 0; i < 8; i++) {
        float2 c0 = unpack2(acc[i][0]), c1 = unpack2(acc[i][1]);
        float2 c2 = unpack2(acc[i][2]), c3 = unpack2(acc[i][3]);
        float* crow = Cb + (long)(m0 + ty * 8 + i) * N + n0 + tx * 8;
        *(float4*)crow       = make_float4(c0.x, c0.y, c1.x, c1.y);
        *(float4*)(crow + 4) = make_float4(c2.x, c2.y, c3.x, c3.y);
    }
}

// ---------------------------------------------------------------------------
// Sum projection K-split parts: g_qp(16) -> g_q, g_kp(4) -> g_k.
// ---------------------------------------------------------------------------
#define QN (kB * kDEC * kU / 4)    // 32768 float4
#define KN (kB * kENC * kU / 4)    // 131072 float4
__global__ __launch_bounds__(256) void reduce_qk_kernel()
{
    int idx = blockIdx.x * 256 + threadIdx.x;
    if (idx < QN) {
        const float4* p = (const float4*)g_qp;
        float4 s = make_float4(0.f, 0.f, 0.f, 0.f);
#pragma unroll
        for (int j = 0; j < QSPLIT; j++) {
            float4 v = p[idx + j * (QP_STRIDE / 4)];
            s.x += v.x; s.y += v.y; s.z += v.z; s.w += v.w;
        }
        ((float4*)g_q)[idx] = s;
    } else {
        int i = idx - QN;
        const float4* p = (const float4*)g_kp;
        float4 s = make_float4(0.f, 0.f, 0.f, 0.f);
#pragma unroll
        for (int j = 0; j < KSPLIT; j++) {
            float4 v = p[i + j * (KP_STRIDE / 4)];
            s.x += v.x; s.y += v.y; s.z += v.z; s.w += v.w;
        }
        ((float4*)g_k)[i] = s;
    }
}

// ---------------------------------------------------------------------------
// ctx = sum of 4 K-split parts per batch.
// ---------------------------------------------------------------------------
__global__ __launch_bounds__(256) void reduce_ctx_kernel(float4* __restrict__ out)
{
    const float4* p = (const float4*)g_cp;
    const int idx = blockIdx.x * 256 + threadIdx.x;
    const int slice = CP_STRIDE / 4;
    const int b = idx / slice;
    const int i = idx - b * slice;
    const float4* base = p + (long)(b * CSPLIT) * slice + i;
    float4 r0 = base[0], r1 = base[slice], r2 = base[2 * slice], r3 = base[3 * slice];
    out[idx] = make_float4(r0.x + r1.x + r2.x + r3.x,
                           r0.y + r1.y + r2.y + r3.y,
                           r0.z + r1.z + r2.z + r3.z,
                           r0.w + r1.w + r2.w + r3.w);
}

// ---------------------------------------------------------------------------
// Additive scores (masked) -> g_sc. One block = (b, 8 queries, 512 enc half).
// grid (2, 32, 4): x = enc half, y = q-tile, z = batch. 256 threads.
// Warp w owns query q0+w; lane handles 4 e-rows per 128-row k tile.
// ---------------------------------------------------------------------------
__global__ __launch_bounds__(256) void score_kernel(
    const float* __restrict__ scale, const int* __restrict__ mask)
{
    extern __shared__ float sm[];
    float* qs  = sm;                  // 8 * 128
    float* scl = qs + 8 * kU;         // 128
    float* ks  = scl + kU;            // 128 * 132

    const int b   = blockIdx.z;
    const int q0  = blockIdx.y * 8;
    const int eh  = blockIdx.x * 512;
    const int tid = threadIdx.x;

#pragma unroll
    for (int i = 0; i < 4; i++)
        qs[tid + i * 256] = g_q[(b * kDEC + q0) * kU + tid + i * 256];
    if (tid < kU) scl[tid] = scale[tid];

    const int q    = tid >> 5;
    const int lane = tid & 31;
    const float* kbase = g_k + (long)b * kENC * kU;
    const int*   mrow  = mask + b * kENC;
    const float* qr = qs + q * kU;
    float* srow = g_sc + (long)(b * kDEC + q0 + q) * kENC;

    for (int et = eh; et < eh + 512; et += 128) {
        __syncthreads();
#pragma unroll
        for (int i = 0; i < 16; i++) {
            int f4  = tid + i * 256;           // 0..4095
            int row = f4 >> 5;
            int col = (f4 & 31) * 4;
            *(float4*)(ks + row * 132 + col) =
                *(const float4*)(kbase + (long)(et + row) * kU + col);
        }
        __syncthreads();

        const float* k0 = ks + (lane +  0) * 132;
        const float* k1 = ks + (lane + 32) * 132;
        const float* k2 = ks + (lane + 64) * 132;
        const float* k3 = ks + (lane + 96) * 132;
        float s0 = 0.f, s1 = 0.f, s2 = 0.f, s3 = 0.f;
#pragma unroll
        for (int u = 0; u < kU; u += 4) {
            float4 qv = *(const float4*)(qr + u);
            float4 sv = *(const float4*)(scl + u);
            float4 a = *(const float4*)(k0 + u);
            float4 c = *(const float4*)(k1 + u);
            float4 d = *(const float4*)(k2 + u);
            float4 e = *(const float4*)(k3 + u);
            s0 = fmaf(sv.x, tanh_approx(qv.x + a.x), s0);
            s0 = fmaf(sv.y, tanh_approx(qv.y + a.y), s0);
            s0 = fmaf(sv.z, tanh_approx(qv.z + a.z), s0);
            s0 = fmaf(sv.w, tanh_approx(qv.w + a.w), s0);
            s1 = fmaf(sv.x, tanh_approx(qv.x + c.x), s1);
            s1 = fmaf(sv.y, tanh_approx(qv.y + c.y), s1);
            s1 = fmaf(sv.z, tanh_approx(qv.z + c.z), s1);
            s1 = fmaf(sv.w, tanh_approx(qv.w + c.w), s1);
            s2 = fmaf(sv.x, tanh_approx(qv.x + d.x), s2);
            s2 = fmaf(sv.y, tanh_approx(qv.y + d.y), s2);
            s2 = fmaf(sv.z, tanh_approx(qv.z + d.z), s2);
            s2 = fmaf(sv.w, tanh_approx(qv.w + d.w), s2);
            s3 = fmaf(sv.x, tanh_approx(qv.x + e.x), s3);
            s3 = fmaf(sv.y, tanh_approx(qv.y + e.y), s3);
            s3 = fmaf(sv.z, tanh_approx(qv.z + e.z), s3);
            s3 = fmaf(sv.w, tanh_approx(qv.w + e.w), s3);
        }
        int e0 = et + lane, e1 = e0 + 32, e2 = e0 + 64, e3 = e0 + 96;
        srow[e0] = (mrow[e0] == 0) ? -1e9f : s0;
        srow[e1] = (mrow[e1] == 0) ? -1e9f : s1;
        srow[e2] = (mrow[e2] == 0) ? -1e9f : s2;
        srow[e3] = (mrow[e3] == 0) ? -1e9f : s3;
    }
}

// ---------------------------------------------------------------------------
// Softmax over g_sc rows -> wts. Warp per row, float4, L2-hot input.
// grid = B*DEC/8 = 128, 256 threads.
// ---------------------------------------------------------------------------
__global__ __launch_bounds__(256) void softmax_kernel(float* __restrict__ wts)
{
    const int r    = blockIdx.x * 8 + (threadIdx.x >> 5);
    const int lane = threadIdx.x & 31;
    const float4* row4 = (const float4*)(g_sc + (long)r * kENC);

    float4 v[8];
    float mx = -3.4e38f;
#pragma unroll
    for (int j = 0; j < 8; j++) {
        v[j] = row4[lane + j * 32];
        mx = fmaxf(mx, fmaxf(fmaxf(v[j].x, v[j].y), fmaxf(v[j].z, v[j].w)));
    }
#pragma unroll
    for (int off = 16; off > 0; off >>= 1)
        mx = fmaxf(mx, __shfl_xor_sync(0xffffffffu, mx, off));

    float ssum = 0.f;
#pragma unroll
    for (int j = 0; j < 8; j++) {
        v[j].x = __expf(v[j].x - mx); v[j].y = __expf(v[j].y - mx);
        v[j].z = __expf(v[j].z - mx); v[j].w = __expf(v[j].w - mx);
        ssum += v[j].x + v[j].y + v[j].z + v[j].w;
    }
#pragma unroll
    for (int off = 16; off > 0; off >>= 1)
        ssum += __shfl_xor_sync(0xffffffffu, ssum, off);
    const float inv = 1.0f / ssum;

    float4* w4 = (float4*)(wts + (long)r * kENC);
#pragma unroll
    for (int j = 0; j < 8; j++)
        w4[lane + j * 32] = make_float4(v[j].x * inv, v[j].y * inv,
                                        v[j].z * inv, v[j].w * inv);
}

// ---------------------------------------------------------------------------
extern "C" void kernel_launch(void* const* d_in, const int* in_sizes, int n_in,
                              void* d_out, int out_size)
{
    const float* query = (const float*)d_in[0];
    const float* value = (const float*)d_in[1];
    const int*   mask  = (const int*)d_in[2];
    const float* W1    = (const float*)d_in[3];
    const float* W2    = (const float*)d_in[4];
    const float* scale = (const float*)d_in[5];

    float* ctx = (float*)d_out;                          // (B, DEC, HID)
    float* wts = ctx + (size_t)kB * kDEC * kHID;         // (B, DEC, ENC)

    float *qp, *kp, *cp;
    cudaGetSymbolAddress((void**)&qp, g_qp);
    cudaGetSymbolAddress((void**)&kp, g_kp);
    cudaGetSymbolAddress((void**)&cp, g_cp);

    cudaFuncSetAttribute(score_kernel,
        cudaFuncAttributeMaxDynamicSharedMemorySize, SCORE_SMEM_BYTES);

    // q projection: (1024,512)@(512,128), split 16 -> 128 blocks
    gemm128<<<dim3(1, 8, QSPLIT), 256>>>(query, W1, qp, 1024, 128, 512, QSPLIT, 0, 0);

    // k projection: (4096,512)@(512,128), split 4 -> 128 blocks
    gemm128<<<dim3(1, 32, KSPLIT), 256>>>(value, W2, kp, 4096, 128, 512, KSPLIT, 0, 0);

    // sum projection parts
    reduce_qk_kernel<<<(QN + KN) / 256, 256>>>();

    // masked scores (grid 256, 2 CTAs/SM)
    score_kernel<<<dim3(2, 32, kB), 256, SCORE_SMEM_BYTES>>>(scale, mask);

    // softmax -> weights
    softmax_kernel<<<kB * kDEC / 8, 256>>>(wts);

    // context: per-batch (256,1024)@(1024,512), split 4 -> 128 blocks
    gemm128<<<dim3(4, 2, kB * CSPLIT), 256>>>(wts, value, cp, 256, 512, 1024, CSPLIT,
                                              (long)kDEC * kENC, (long)kENC * kHID);

    // sum ctx parts -> d_out
    reduce_ctx_kernel<<<(kB * CP_STRIDE / 4) / 256, 256>>>((float4*)ctx);
}